// round 1
// baseline (speedup 1.0000x reference)
#include <cuda_runtime.h>
#include <math_constants.h>

#define NB 32
#define NT 512
#define ND 512
#define NV 1024
#define NL 128
#define NS 257      // 2*NL+1
#define SPAD 288    // padded S stride
#define NM (NB*NT)  // 16384 rows

// Scratch (allocation-free per harness rules)
__device__ float g_logits[(size_t)NM * NV];   // 64 MB
__device__ float g_pext[(size_t)NM * SPAD];   // 18.9 MB
__device__ float g_loss[NB];

// ---------------------------------------------------------------------------
// Kernel 1: logits = x @ W + b   (fp32 SIMT, 128x128x8 tiles, 8x8 per thread)
// ---------------------------------------------------------------------------
__global__ __launch_bounds__(256) void gemm_kernel(const float* __restrict__ A,
                                                   const float* __restrict__ B,
                                                   const float* __restrict__ bias) {
    const int K = ND, N = NV;
    __shared__ float As[8][128];
    __shared__ float Bs[8][128];
    int tid = threadIdx.x;
    int bx = blockIdx.x, by = blockIdx.y;
    const float* Ab = A + (size_t)by * 128 * K;
    const float* Bb = B + bx * 128;
    float* Cb = g_logits + (size_t)by * 128 * N + bx * 128;

    int arow = tid >> 1, acol = (tid & 1) * 4;
    int brow = tid >> 5, bcol = (tid & 31) * 4;
    int ty = tid >> 4, tx = tid & 15;

    float acc[8][8];
#pragma unroll
    for (int i = 0; i < 8; i++)
#pragma unroll
        for (int j = 0; j < 8; j++) acc[i][j] = 0.f;

    for (int k0 = 0; k0 < K; k0 += 8) {
        float4 av = *(const float4*)(Ab + (size_t)arow * K + k0 + acol);
        As[acol + 0][arow] = av.x;
        As[acol + 1][arow] = av.y;
        As[acol + 2][arow] = av.z;
        As[acol + 3][arow] = av.w;
        *(float4*)(&Bs[brow][bcol]) = *(const float4*)(Bb + (size_t)(k0 + brow) * N + bcol);
        __syncthreads();
#pragma unroll
        for (int kk = 0; kk < 8; kk++) {
            float ra[8], rb[8];
            *(float4*)&ra[0] = *(const float4*)&As[kk][ty * 8];
            *(float4*)&ra[4] = *(const float4*)&As[kk][ty * 8 + 4];
            *(float4*)&rb[0] = *(const float4*)&Bs[kk][tx * 8];
            *(float4*)&rb[4] = *(const float4*)&Bs[kk][tx * 8 + 4];
#pragma unroll
            for (int i = 0; i < 8; i++)
#pragma unroll
                for (int j = 0; j < 8; j++) acc[i][j] += ra[i] * rb[j];
        }
        __syncthreads();
    }

    int col0 = bx * 128 + tx * 8;
#pragma unroll
    for (int i = 0; i < 8; i++) {
#pragma unroll
        for (int j0 = 0; j0 < 8; j0 += 4) {
            float4 o;
            o.x = acc[i][j0 + 0] + bias[col0 + j0 + 0];
            o.y = acc[i][j0 + 1] + bias[col0 + j0 + 1];
            o.z = acc[i][j0 + 2] + bias[col0 + j0 + 2];
            o.w = acc[i][j0 + 3] + bias[col0 + j0 + 3];
            *(float4*)(Cb + (size_t)(ty * 8 + i) * N + tx * 8 + j0) = o;
        }
    }
}

// ---------------------------------------------------------------------------
// Kernel 2: per-row softmax over V, emit PROBABILITIES at extended labels
//           p_ext[row][s]: even s -> p(blank), odd s -> p(target[(s-1)/2])
// ---------------------------------------------------------------------------
__global__ __launch_bounds__(128) void softmax_kernel(const int* __restrict__ target) {
    int warp = threadIdx.x >> 5, lane = threadIdx.x & 31;
    int row = blockIdx.x * 4 + warp;          // 0..16383
    int b = row >> 9;                          // row / 512
    const float* lg = g_logits + (size_t)row * NV;

    float m = -CUDART_INF_F;
    float4 v[8];
#pragma unroll
    for (int i = 0; i < 8; i++) {
        v[i] = *(const float4*)(lg + i * 128 + lane * 4);
        m = fmaxf(m, fmaxf(fmaxf(v[i].x, v[i].y), fmaxf(v[i].z, v[i].w)));
    }
#pragma unroll
    for (int o = 16; o > 0; o >>= 1) m = fmaxf(m, __shfl_xor_sync(0xffffffffu, m, o));

    float se = 0.f;
#pragma unroll
    for (int i = 0; i < 8; i++)
        se += __expf(v[i].x - m) + __expf(v[i].y - m) + __expf(v[i].z - m) + __expf(v[i].w - m);
#pragma unroll
    for (int o = 16; o > 0; o >>= 1) se += __shfl_xor_sync(0xffffffffu, se, o);

    float inv = 1.f / se;
    float pblank = __expf(lg[0] - m) * inv;

    float* P = g_pext + (size_t)row * SPAD;
    const int* tg = target + b * NL;
    for (int j = lane; j < NL; j += 32) {
        int lab = tg[j];
        P[2 * j + 1] = __expf(lg[lab] - m) * inv;
    }
    for (int j = lane; j <= NL; j += 32) P[2 * j] = pblank;
    if (lane < 31) P[NS + lane] = 0.f;   // zero the pad (s = 257..287)
}

// ---------------------------------------------------------------------------
// Kernel 3: CTC forward recursion in probability domain with rescaling.
//           One warp per batch; lane owns 9 contiguous s positions.
// ---------------------------------------------------------------------------
__global__ __launch_bounds__(32) void ctc_kernel(const int* __restrict__ target,
                                                 const int* __restrict__ in_len,
                                                 const int* __restrict__ tgt_len) {
    int b = blockIdx.x;
    int lane = threadIdx.x;
    int s0 = lane * 9;
    const int* tg = target + b * NL;

    // skip flags: odd s >= 3 where target[(s-1)/2] != target[(s-3)/2]
    unsigned skipm = 0;
#pragma unroll
    for (int k = 0; k < 9; k++) {
        int s = s0 + k;
        if (s >= 3 && s < NS && (s & 1)) {
            int j = (s - 1) >> 1;
            if (tg[j] != tg[j - 1]) skipm |= (1u << k);
        }
    }

    const float* P = g_pext + (size_t)b * NT * SPAD;
    int TL = in_len[b];
    int tl = tgt_len[b];
    int send1 = 2 * tl - 1, send2 = 2 * tl;

    float a[9];
#pragma unroll
    for (int k = 0; k < 9; k++) {
        int s = s0 + k;
        float p = (s < NS) ? P[s] : 0.f;
        a[k] = (s < 2) ? p : 0.f;
    }

    float logscale = 0.f;
    float ll = -CUDART_INF_F;

    if (TL == 1) {
        float part = 0.f;
#pragma unroll
        for (int k = 0; k < 9; k++) {
            int s = s0 + k;
            part += (s == send1 || s == send2) ? a[k] : 0.f;
        }
#pragma unroll
        for (int o = 16; o > 0; o >>= 1) part += __shfl_xor_sync(0xffffffffu, part, o);
        ll = __logf(part);
    }

    // prefetch pipeline: pA = p(t), pB = p(t+1)
    float pA[9], pB[9];
#pragma unroll
    for (int k = 0; k < 9; k++) { int s = s0 + k; pA[k] = (s < NS) ? P[SPAD + s] : 0.f; }
#pragma unroll
    for (int k = 0; k < 9; k++) { int s = s0 + k; pB[k] = (s < NS) ? P[2 * SPAD + s] : 0.f; }

    for (int t = 1; t < NT; t++) {
        float pN[9];
        if (t + 2 < NT) {
            const float* Pt = P + (size_t)(t + 2) * SPAD;
#pragma unroll
            for (int k = 0; k < 9; k++) { int s = s0 + k; pN[k] = (s < NS) ? Pt[s] : 0.f; }
        } else {
#pragma unroll
            for (int k = 0; k < 9; k++) pN[k] = 0.f;
        }

        float up1 = __shfl_up_sync(0xffffffffu, a[8], 1);  // s0-1
        float up2 = __shfl_up_sync(0xffffffffu, a[7], 1);  // s0-2
        if (lane == 0) { up1 = 0.f; up2 = 0.f; }

        float na[9];
#pragma unroll
        for (int k = 0; k < 9; k++) {
            float sm1 = (k >= 1) ? a[k - 1] : up1;
            float sm2 = (k >= 2) ? a[k - 2] : ((k == 1) ? up1 : up2);
            float c = a[k] + sm1;
            if ((skipm >> k) & 1u) c += sm2;
            na[k] = c * pA[k];
        }
#pragma unroll
        for (int k = 0; k < 9; k++) a[k] = na[k];

        if (t == TL - 1) {
            float part = 0.f;
#pragma unroll
            for (int k = 0; k < 9; k++) {
                int s = s0 + k;
                part += (s == send1 || s == send2) ? a[k] : 0.f;
            }
#pragma unroll
            for (int o = 16; o > 0; o >>= 1) part += __shfl_xor_sync(0xffffffffu, part, o);
            ll = logscale + __logf(part);
        }

        if ((t & 3) == 3) {
            float tot = 0.f;
#pragma unroll
            for (int k = 0; k < 9; k++) tot += a[k];
#pragma unroll
            for (int o = 16; o > 0; o >>= 1) tot += __shfl_xor_sync(0xffffffffu, tot, o);
            if (tot > 0.f) {
                float sc = 1.f / tot;
                logscale += __logf(tot);
#pragma unroll
                for (int k = 0; k < 9; k++) a[k] *= sc;
            }
        }

#pragma unroll
        for (int k = 0; k < 9; k++) { pA[k] = pB[k]; pB[k] = pN[k]; }
    }

    if (lane == 0) {
        float nll = -ll;
        if (!(nll < 1e29f)) nll = 0.f;   // zero_infinity (also catches NaN)
        g_loss[b] = nll / fmaxf((float)tl, 1.f);
    }
}

// ---------------------------------------------------------------------------
// Kernel 4: mean over batch
// ---------------------------------------------------------------------------
__global__ void reduce_kernel(float* __restrict__ out) {
    int lane = threadIdx.x;
    float v = (lane < NB) ? g_loss[lane] : 0.f;
#pragma unroll
    for (int o = 16; o > 0; o >>= 1) v += __shfl_xor_sync(0xffffffffu, v, o);
    if (lane == 0) out[0] = v * (1.f / NB);
}

extern "C" void kernel_launch(void* const* d_in, const int* in_sizes, int n_in,
                              void* d_out, int out_size) {
    const float* x = (const float*)d_in[0];        // [B,T,D]
    const float* W = (const float*)d_in[1];        // [D,V]
    const float* bias = (const float*)d_in[2];     // [V]
    const int* target = (const int*)d_in[3];       // [B,L]
    const int* in_len = (const int*)d_in[4];       // [B]
    const int* tgt_len = (const int*)d_in[5];      // [B]

    dim3 gg(NV / 128, NM / 128);
    gemm_kernel<<<gg, 256>>>(x, W, bias);
    softmax_kernel<<<NM / 4, 128>>>(target);
    ctc_kernel<<<NB, 32>>>(target, in_len, tgt_len);
    reduce_kernel<<<1, 32>>>((float*)d_out);
}